// round 2
// baseline (speedup 1.0000x reference)
#include <cuda_runtime.h>

#define NB 4096
#define ND 1024
#define NF 512
#define NEG_INF (-1e30f)

// ---------------- scratch (device globals; no allocations allowed) ----------
__device__ float g_proj[3][NB * NF];          // 24 MB projected modalities (filled in place)
__device__ float g_norm[3][NB];               // row L2 norms (pre-fill)
__device__ int   g_rows[3][NB];               // compacted missing-row lists
__device__ int   g_cnt[3];                    // missing counts
__device__ float g_sim[(size_t)NB * NB];      // 64 MB sim scratch (reused per modality)
__device__ float g_h[(size_t)NB * NF];        // 8 MB hidden layer

// ---------------- tiny setup kernels ----------------------------------------
__global__ void k_reset() {
    if (threadIdx.x < 3) g_cnt[threadIdx.x] = 0;
}

__global__ void k_build(const int* __restrict__ mi) {
    int i = blockIdx.x * blockDim.x + threadIdx.x;
    if (i < NB) {
        int t = mi[i];
        if (t >= 1 && t <= 3) {
            int p = atomicAdd(&g_cnt[t - 1], 1);
            g_rows[t - 1][p] = i;
        }
    }
}

// ---------------- projection GEMM: proj[z] = X_z @ W_z + b_z ----------------
// 64x64 tile, BK=16, 256 threads, 4x4 micro-tile.
__global__ void __launch_bounds__(256) k_proj(
    const float* __restrict__ A0, const float* __restrict__ A1, const float* __restrict__ A2,
    const float* __restrict__ Wl, const float* __restrict__ Wv, const float* __restrict__ Wa,
    const float* __restrict__ bl, const float* __restrict__ bv, const float* __restrict__ ba)
{
    const int z = blockIdx.z;
    const float* A    = (z == 0) ? A0 : (z == 1) ? A1 : A2;
    const float* W    = (z == 0) ? Wl : (z == 1) ? Wv : Wa;
    const float* bias = (z == 0) ? bl : (z == 1) ? bv : ba;
    float* C = g_proj[z];
    const int K = ND, N = NF;

    __shared__ float As[16][64];
    __shared__ float Bs[16][64];

    const int m0 = blockIdx.y * 64, n0 = blockIdx.x * 64;
    const int tx = threadIdx.x & 15, ty = threadIdx.x >> 4;
    const int ar = threadIdx.x >> 2, ac = (threadIdx.x & 3) * 4;   // A tile loader
    const int br = threadIdx.x >> 4, bc = (threadIdx.x & 15) * 4;  // B tile loader

    float acc[4][4] = {};

    for (int k0 = 0; k0 < K; k0 += 16) {
        float4 va = *(const float4*)(A + (size_t)(m0 + ar) * K + k0 + ac);
        As[ac + 0][ar] = va.x; As[ac + 1][ar] = va.y;
        As[ac + 2][ar] = va.z; As[ac + 3][ar] = va.w;
        float4 vb = *(const float4*)(W + (size_t)(k0 + br) * N + n0 + bc);
        *(float4*)&Bs[br][bc] = vb;
        __syncthreads();
#pragma unroll
        for (int k = 0; k < 16; k++) {
            float a[4], b[4];
            *(float4*)a = *(const float4*)&As[k][ty * 4];
            *(float4*)b = *(const float4*)&Bs[k][tx * 4];
#pragma unroll
            for (int i = 0; i < 4; i++)
#pragma unroll
                for (int j = 0; j < 4; j++) acc[i][j] += a[i] * b[j];
        }
        __syncthreads();
    }
#pragma unroll
    for (int i = 0; i < 4; i++) {
        float4 o;
        o.x = acc[i][0] + bias[n0 + tx * 4 + 0];
        o.y = acc[i][1] + bias[n0 + tx * 4 + 1];
        o.z = acc[i][2] + bias[n0 + tx * 4 + 2];
        o.w = acc[i][3] + bias[n0 + tx * 4 + 3];
        *(float4*)(C + (size_t)(m0 + ty * 4 + i) * N + n0 + tx * 4) = o;
    }
}

// ---------------- row norms (pre-fill) ---------------------------------------
__global__ void __launch_bounds__(128) k_norm() {
    const int z = blockIdx.z;
    const int warp = threadIdx.x >> 5, lane = threadIdx.x & 31;
    const int row = blockIdx.x * 4 + warp;
    const float* p = g_proj[z] + (size_t)row * NF;
    float s = 0.f;
    for (int f = lane; f < NF; f += 32) { float v = p[f]; s += v * v; }
#pragma unroll
    for (int o = 16; o; o >>= 1) s += __shfl_xor_sync(0xffffffffu, s, o);
    if (lane == 0) g_norm[z][row] = sqrtf(s);
}

// ---------------- sim GEMM (NT): sim[m, n] = <proj[rows[m]], proj[n]> --------
__global__ void __launch_bounds__(256) k_sim(int z) {
    const int cnt = g_cnt[z];
    const int m0 = blockIdx.y * 64;
    if (m0 >= cnt) return;
    const int n0 = blockIdx.x * 64;
    const float* P = g_proj[z];

    __shared__ float As[16][64];
    __shared__ float Bs[16][64];
    __shared__ int rowi[64];
    if (threadIdx.x < 64) {
        int m = m0 + threadIdx.x;
        rowi[threadIdx.x] = g_rows[z][m < cnt ? m : cnt - 1];
    }
    __syncthreads();

    const int tx = threadIdx.x & 15, ty = threadIdx.x >> 4;
    const int ar = threadIdx.x >> 2, ac = (threadIdx.x & 3) * 4;
    float acc[4][4] = {};

    for (int k0 = 0; k0 < NF; k0 += 16) {
        float4 va = *(const float4*)(P + (size_t)rowi[ar] * NF + k0 + ac);
        As[ac + 0][ar] = va.x; As[ac + 1][ar] = va.y;
        As[ac + 2][ar] = va.z; As[ac + 3][ar] = va.w;
        float4 vb = *(const float4*)(P + (size_t)(n0 + ar) * NF + k0 + ac);
        Bs[ac + 0][ar] = vb.x; Bs[ac + 1][ar] = vb.y;
        Bs[ac + 2][ar] = vb.z; Bs[ac + 3][ar] = vb.w;
        __syncthreads();
#pragma unroll
        for (int k = 0; k < 16; k++) {
            float a[4], b[4];
            *(float4*)a = *(const float4*)&As[k][ty * 4];
            *(float4*)b = *(const float4*)&Bs[k][tx * 4];
#pragma unroll
            for (int i = 0; i < 4; i++)
#pragma unroll
                for (int j = 0; j < 4; j++) acc[i][j] += a[i] * b[j];
        }
        __syncthreads();
    }
#pragma unroll
    for (int i = 0; i < 4; i++) {
        int m = m0 + ty * 4 + i;
        if (m < cnt) {
            float4 o = {acc[i][0], acc[i][1], acc[i][2], acc[i][3]};
            *(float4*)(g_sim + (size_t)m * NB + n0 + tx * 4) = o;
        }
    }
}

// ---------------- top-3 + softmax + fill -------------------------------------
__device__ __forceinline__ bool better(float v, int i, float V, int I) {
    return v > V || (v == V && i < I);  // jax top_k tie-break: lower index wins
}

__global__ void __launch_bounds__(128) k_topk(int z, const int* __restrict__ mi) {
    const int m = blockIdx.x;
    const int cnt = g_cnt[z];
    if (m >= cnt) return;
    const int r = g_rows[z][m];
    float* P = g_proj[z];
    const float* nrm = g_norm[z];
    const float ni = nrm[r];
    const float* srow = g_sim + (size_t)m * NB;

    float v0 = NEG_INF, v1 = NEG_INF, v2 = NEG_INF;
    int   i0 = NB, i1 = NB, i2 = NB;
    for (int n = threadIdx.x; n < NB; n += 128) {
        if (mi[n] == z + 1) continue;  // missing columns excluded (incl. self)
        float s = srow[n] / fmaxf(ni * nrm[n], 1e-8f);
        if (better(s, n, v0, i0)) { v2 = v1; i2 = i1; v1 = v0; i1 = i0; v0 = s; i0 = n; }
        else if (better(s, n, v1, i1)) { v2 = v1; i2 = i1; v1 = s; i1 = n; }
        else if (better(s, n, v2, i2)) { v2 = s; i2 = n; }
    }

    __shared__ float sv[384];
    __shared__ int   si[384];
    sv[threadIdx.x * 3 + 0] = v0; si[threadIdx.x * 3 + 0] = i0;
    sv[threadIdx.x * 3 + 1] = v1; si[threadIdx.x * 3 + 1] = i1;
    sv[threadIdx.x * 3 + 2] = v2; si[threadIdx.x * 3 + 2] = i2;
    __syncthreads();

    __shared__ float w[3];
    __shared__ int   bi[3];
    if (threadIdx.x == 0) {
        float b0 = NEG_INF, b1 = NEG_INF, b2 = NEG_INF;
        int   j0 = NB, j1 = NB, j2 = NB;
        for (int t = 0; t < 384; t++) {
            float s = sv[t]; int n = si[t];
            if (better(s, n, b0, j0)) { b2 = b1; j2 = j1; b1 = b0; j1 = j0; b0 = s; j0 = n; }
            else if (better(s, n, b1, j1)) { b2 = b1; j2 = j1; b1 = s; j1 = n; }
            else if (better(s, n, b2, j2)) { b2 = s; j2 = n; }
        }
        float e0 = 1.0f, e1 = expf(b1 - b0), e2 = expf(b2 - b0);
        float inv = 1.0f / (e0 + e1 + e2);
        w[0] = e0 * inv; w[1] = e1 * inv; w[2] = e2 * inv;
        bi[0] = j0; bi[1] = j1; bi[2] = j2;
    }
    __syncthreads();

    const float* f0 = P + (size_t)bi[0] * NF;
    const float* f1 = P + (size_t)bi[1] * NF;
    const float* f2 = P + (size_t)bi[2] * NF;
    const float w0 = w[0], w1 = w[1], w2 = w[2];
    for (int f = threadIdx.x; f < NF; f += 128)
        P[(size_t)r * NF + f] = w0 * f0[f] + w1 * f1[f] + w2 * f2[f];
}

// ---------------- fused concat GEMM + ReLU: h = relu([p0|p1|p2] @ W1 + b1) ---
__global__ void __launch_bounds__(256) k_h(const float* __restrict__ W1,
                                           const float* __restrict__ b1) {
    __shared__ float As[16][64];
    __shared__ float Bs[16][64];
    const int m0 = blockIdx.y * 64, n0 = blockIdx.x * 64;
    const int tx = threadIdx.x & 15, ty = threadIdx.x >> 4;
    const int ar = threadIdx.x >> 2, ac = (threadIdx.x & 3) * 4;
    const int br = threadIdx.x >> 4, bc = (threadIdx.x & 15) * 4;
    float acc[4][4] = {};

    for (int k0 = 0; k0 < 3 * NF; k0 += 16) {
        const float* A = g_proj[k0 >> 9];   // BK tile never crosses a 512 boundary
        const int kc = k0 & 511;
        float4 va = *(const float4*)(A + (size_t)(m0 + ar) * NF + kc + ac);
        As[ac + 0][ar] = va.x; As[ac + 1][ar] = va.y;
        As[ac + 2][ar] = va.z; As[ac + 3][ar] = va.w;
        float4 vb = *(const float4*)(W1 + (size_t)(k0 + br) * NF + n0 + bc);
        *(float4*)&Bs[br][bc] = vb;
        __syncthreads();
#pragma unroll
        for (int k = 0; k < 16; k++) {
            float a[4], b[4];
            *(float4*)a = *(const float4*)&As[k][ty * 4];
            *(float4*)b = *(const float4*)&Bs[k][tx * 4];
#pragma unroll
            for (int i = 0; i < 4; i++)
#pragma unroll
                for (int j = 0; j < 4; j++) acc[i][j] += a[i] * b[j];
        }
        __syncthreads();
    }
#pragma unroll
    for (int i = 0; i < 4; i++) {
        float4 o;
        o.x = fmaxf(acc[i][0] + b1[n0 + tx * 4 + 0], 0.f);
        o.y = fmaxf(acc[i][1] + b1[n0 + tx * 4 + 1], 0.f);
        o.z = fmaxf(acc[i][2] + b1[n0 + tx * 4 + 2], 0.f);
        o.w = fmaxf(acc[i][3] + b1[n0 + tx * 4 + 3], 0.f);
        *(float4*)(g_h + (size_t)(m0 + ty * 4 + i) * NF + n0 + tx * 4) = o;
    }
}

// ---------------- out[m] = h[m,:] . W2 + b2 ----------------------------------
__global__ void __launch_bounds__(128) k_out(const float* __restrict__ W2,
                                             const float* __restrict__ b2,
                                             float* __restrict__ out) {
    const int m = blockIdx.x;
    float s = 0.f;
    for (int n = threadIdx.x; n < NF; n += 128)
        s += g_h[(size_t)m * NF + n] * W2[n];
#pragma unroll
    for (int o = 16; o; o >>= 1) s += __shfl_xor_sync(0xffffffffu, s, o);
    __shared__ float ps[4];
    if ((threadIdx.x & 31) == 0) ps[threadIdx.x >> 5] = s;
    __syncthreads();
    if (threadIdx.x == 0) out[m] = ps[0] + ps[1] + ps[2] + ps[3] + b2[0];
}

// ---------------- launcher ----------------------------------------------------
extern "C" void kernel_launch(void* const* d_in, const int* in_sizes, int n_in,
                              void* d_out, int out_size) {
    const float* lang = (const float*)d_in[0];
    const float* vid  = (const float*)d_in[1];
    const float* aud  = (const float*)d_in[2];
    const int*   mi   = (const int*)d_in[3];
    const float* Wl   = (const float*)d_in[4];
    const float* bl   = (const float*)d_in[5];
    const float* Wv   = (const float*)d_in[6];
    const float* bv   = (const float*)d_in[7];
    const float* Wa   = (const float*)d_in[8];
    const float* ba   = (const float*)d_in[9];
    const float* W1   = (const float*)d_in[10];
    const float* b1   = (const float*)d_in[11];
    const float* W2   = (const float*)d_in[12];
    const float* b2   = (const float*)d_in[13];
    float* out = (float*)d_out;

    k_reset<<<1, 32>>>();
    k_build<<<NB / 256, 256>>>(mi);
    k_proj<<<dim3(NF / 64, NB / 64, 3), 256>>>(lang, vid, aud, Wl, Wv, Wa, bl, bv, ba);
    k_norm<<<dim3(NB / 4, 1, 3), 128>>>();
    for (int z = 0; z < 3; z++) {
        k_sim<<<dim3(NB / 64, NB / 64), 256>>>(z);
        k_topk<<<NB, 128>>>(z, mi);
    }
    k_h<<<dim3(NF / 64, NB / 64), 256>>>(W1, b1);
    k_out<<<NB, 128>>>(W2, b2, out);
}